// round 1
// baseline (speedup 1.0000x reference)
#include <cuda_runtime.h>
#include <cuda_bf16.h>

#define HH 64
#define WW 64
#define CC 256
#define OCC 256
#define BK 8

// Scratch weight, transposed for conv-friendly loads: g_wT[tap][in_ch][out_ch]
__device__ float g_wT[9 * 256 * 256];

// ---------------------------------------------------------------------------
// Kernel 1: hypernetwork weight generation.
// a[l,b,d] = sum_n W1[b,d,n] * z[l,n] + B1[b,d]
// K[l,b,k] = sum_d W2[b,k,d] * a[l,b,d] + B2[b,k]
// weight[o_blk*16+b2][i_blk*16+b][kh][kw] = K[l=o_blk*16+i_blk][b][b2*9+kh*3+kw]
// stored as g_wT[(tap*256 + in)*256 + out]
// ---------------------------------------------------------------------------
__global__ void weight_gen_kernel(const float* __restrict__ z,
                                  const float* __restrict__ W1,
                                  const float* __restrict__ B1,
                                  const float* __restrict__ W2,
                                  const float* __restrict__ B2) {
    __shared__ float z_s[64];
    __shared__ float a_s[16 * 64];
    const int l = blockIdx.x;
    const int t = threadIdx.x;

    if (t < 64) z_s[t] = z[l * 64 + t];
    __syncthreads();

    // layer 1: 1024 entries, 256 threads -> 4 each
    for (int i = t; i < 16 * 64; i += 256) {
        const int b = i >> 6, d = i & 63;
        float s = B1[b * 64 + d];
        const float* w = W1 + (b * 64 + d) * 64;
        #pragma unroll 16
        for (int n = 0; n < 64; ++n) s += w[n] * z_s[n];
        a_s[i] = s;
    }
    __syncthreads();

    const int o_blk = l >> 4;
    const int i_blk = l & 15;

    // layer 2 + scatter: 2304 entries, 9 each
    for (int i = t; i < 16 * 144; i += 256) {
        const int b = i / 144, k = i - b * 144;
        float s = B2[b * 144 + k];
        const float* w = W2 + (b * 144 + k) * 64;
        const float* a = a_s + b * 64;
        #pragma unroll 16
        for (int d = 0; d < 64; ++d) s += w[d] * a[d];
        const int b2 = k / 9;
        const int tap = k - b2 * 9;
        const int o = o_blk * 16 + b2;
        const int ic = i_blk * 16 + b;
        g_wT[(tap * 256 + ic) * 256 + o] = s;
    }
}

// ---------------------------------------------------------------------------
// Kernel 2: direct 3x3 conv, pad 1, fp32.
// CTA tile: 1 image, 2 rows x 64 cols (128 px), 64 out channels.
// 128 threads, each computes 8 px x 8 oc. K-loop over 8-input-channel slabs.
// ---------------------------------------------------------------------------
__global__ __launch_bounds__(128, 4)
void conv_kernel(const float* __restrict__ x, float* __restrict__ out) {
    __shared__ float a_s[BK][4][66];      // halo: BK ch x 4 rows x 66 cols
    __shared__ float b_s[9][BK][64];      // weights: tap x ch x 64 oc

    const int rp  = blockIdx.x;           // row pair (0..31)
    const int n   = blockIdx.y;           // image (0..31)
    const int ocb = blockIdx.z;           // oc block (0..3)
    const int t   = threadIdx.x;
    const int tx  = t & 15;               // pixel group (0..15)
    const int ty  = t >> 4;               // oc group (0..7)
    const int y0  = rp * 2;
    const int oc_base = ocb * 64;

    float acc[8][8];
    #pragma unroll
    for (int i = 0; i < 8; ++i)
        #pragma unroll
        for (int j = 0; j < 8; ++j) acc[i][j] = 0.f;

    for (int c0 = 0; c0 < CC; c0 += BK) {
        __syncthreads();   // protect smem reuse from previous iteration

        // ---- load input halo tile ----
        for (int idx = t; idx < BK * 4 * 66; idx += 128) {
            const int c = idx / 264;
            int rem = idx - c * 264;
            const int r = rem / 66;
            const int col = rem - r * 66;
            const int gy = y0 - 1 + r;
            const int gx = col - 1;
            float v = 0.f;
            if ((unsigned)gy < 64u && (unsigned)gx < 64u)
                v = x[(((n * CC + c0 + c) * HH + gy) * WW) + gx];
            a_s[c][r][col] = v;
        }
        // ---- load weight tile (coalesced along oc) ----
        for (int idx = t; idx < 9 * BK * 64; idx += 128) {
            const int tap = idx / (BK * 64);
            int rem = idx - tap * (BK * 64);
            const int c = rem >> 6, o = rem & 63;
            b_s[tap][c][o] = g_wT[(tap * 256 + c0 + c) * 256 + oc_base + o];
        }
        __syncthreads();

        // ---- compute ----
        #pragma unroll 2
        for (int c = 0; c < BK; ++c) {
            #pragma unroll
            for (int kh = 0; kh < 3; ++kh) {
                #pragma unroll
                for (int kw = 0; kw < 3; ++kw) {
                    float av[8];
                    #pragma unroll
                    for (int j = 0; j < 8; ++j) {
                        // pixel p = tx + 16*j ; row = j>>2 ; col = tx + 16*(j&3)
                        av[j] = a_s[c][(j >> 2) + kh][tx + ((j & 3) << 4) + kw];
                    }
                    float bv[8];
                    #pragma unroll
                    for (int i = 0; i < 8; ++i)
                        bv[i] = b_s[kh * 3 + kw][c][ty * 8 + i];
                    #pragma unroll
                    for (int i = 0; i < 8; ++i)
                        #pragma unroll
                        for (int j = 0; j < 8; ++j)
                            acc[i][j] += av[j] * bv[i];
                }
            }
        }
    }

    // ---- write output ----
    #pragma unroll
    for (int i = 0; i < 8; ++i) {
        const int o = oc_base + ty * 8 + i;
        #pragma unroll
        for (int j = 0; j < 8; ++j) {
            const int y = y0 + (j >> 2);
            const int col = tx + ((j & 3) << 4);
            out[(((n * OCC + o) * HH + y) * WW) + col] = acc[i][j];
        }
    }
}

extern "C" void kernel_launch(void* const* d_in, const int* in_sizes, int n_in,
                              void* d_out, int out_size) {
    const float* x  = (const float*)d_in[0];
    const float* z  = (const float*)d_in[1];
    const float* W1 = (const float*)d_in[2];
    const float* B1 = (const float*)d_in[3];
    const float* W2 = (const float*)d_in[4];
    const float* B2 = (const float*)d_in[5];
    float* out = (float*)d_out;

    weight_gen_kernel<<<256, 256>>>(z, W1, B1, W2, B2);
    dim3 grid(32, 32, 4);
    conv_kernel<<<grid, 128>>>(x, out);
}

// round 3
// speedup vs baseline: 1.5999x; 1.5999x over previous
#include <cuda_runtime.h>
#include <cuda_bf16.h>
#include <cstdint>

// ===========================================================================
// HyperConvS: weight-gen -> NHWC bf16 hi/lo convert -> implicit GEMM conv
// using warp-level mma.sync (bf16x3 split, fp32 accum). Baseline-PTX only
// (no tcgen05 -- harness compiles via compute_103 virtual arch).
// ===========================================================================

#define HH 64
#define WW 64
#define CC 256
#define OCC 256

__device__ __nv_bfloat16 g_xhi[32 * 64 * 64 * 256];   // NHWC
__device__ __nv_bfloat16 g_xlo[32 * 64 * 64 * 256];
__device__ __nv_bfloat16 g_whi[9 * 256 * 256];        // [tap][oc][ic]
__device__ __nv_bfloat16 g_wlo[9 * 256 * 256];

// ---- helpers ----
__device__ __forceinline__ uint32_t smem_u32(const void* p) {
    uint32_t a;
    asm("{ .reg .u64 t; cvta.to.shared.u64 t, %1; cvt.u32.u64 %0, t; }"
        : "=r"(a) : "l"(p));
    return a;
}

__device__ __forceinline__ void cp_async16(uint32_t dst, const void* src, uint32_t nbytes) {
    asm volatile("cp.async.cg.shared.global [%0], [%1], 16, %2;"
                 :: "r"(dst), "l"(src), "r"(nbytes) : "memory");
}
__device__ __forceinline__ void cp_commit() {
    asm volatile("cp.async.commit_group;" ::: "memory");
}
template <int N>
__device__ __forceinline__ void cp_wait() {
    asm volatile("cp.async.wait_group %0;" :: "n"(N) : "memory");
}

__device__ __forceinline__ void ldmx4(uint32_t* r, uint32_t addr) {
    asm volatile("ldmatrix.sync.aligned.m8n8.x4.shared.b16 {%0,%1,%2,%3}, [%4];"
                 : "=r"(r[0]), "=r"(r[1]), "=r"(r[2]), "=r"(r[3]) : "r"(addr));
}

__device__ __forceinline__ void mma16816(float* c, const uint32_t* a, const uint32_t* b) {
    asm volatile(
        "mma.sync.aligned.m16n8k16.row.col.f32.bf16.bf16.f32 "
        "{%0,%1,%2,%3}, {%4,%5,%6,%7}, {%8,%9}, {%0,%1,%2,%3};"
        : "+f"(c[0]), "+f"(c[1]), "+f"(c[2]), "+f"(c[3])
        : "r"(a[0]), "r"(a[1]), "r"(a[2]), "r"(a[3]), "r"(b[0]), "r"(b[1]));
}

// ---------------------------------------------------------------------------
// Kernel 1: hypernetwork weight generation -> bf16 hi/lo at [tap][oc][ic]
// ---------------------------------------------------------------------------
__global__ void weight_gen_kernel(const float* __restrict__ z,
                                  const float* __restrict__ W1,
                                  const float* __restrict__ B1,
                                  const float* __restrict__ W2,
                                  const float* __restrict__ B2) {
    __shared__ float z_s[64];
    __shared__ float a_s[16 * 64];
    const int l = blockIdx.x;
    const int t = threadIdx.x;

    if (t < 64) z_s[t] = z[l * 64 + t];
    __syncthreads();

    for (int i = t; i < 16 * 64; i += 256) {
        const int b = i >> 6, d = i & 63;
        float s = B1[b * 64 + d];
        const float* w = W1 + (b * 64 + d) * 64;
        #pragma unroll 16
        for (int n = 0; n < 64; ++n) s += w[n] * z_s[n];
        a_s[i] = s;
    }
    __syncthreads();

    const int o_blk = l >> 4;
    const int i_blk = l & 15;

    for (int i = t; i < 16 * 144; i += 256) {
        const int b = i / 144, k = i - b * 144;
        float s = B2[b * 144 + k];
        const float* w = W2 + (b * 144 + k) * 64;
        const float* a = a_s + b * 64;
        #pragma unroll 16
        for (int d = 0; d < 64; ++d) s += w[d] * a[d];
        const int b2 = k / 9;
        const int tap = k - b2 * 9;
        const int o = o_blk * 16 + b2;
        const int ic = i_blk * 16 + b;
        __nv_bfloat16 hi = __float2bfloat16(s);
        __nv_bfloat16 lo = __float2bfloat16(s - __bfloat162float(hi));
        g_whi[(tap * 256 + o) * 256 + ic] = hi;
        g_wlo[(tap * 256 + o) * 256 + ic] = lo;
    }
}

// ---------------------------------------------------------------------------
// Kernel 2: NCHW fp32 -> NHWC bf16 hi/lo transpose.
// ---------------------------------------------------------------------------
__global__ __launch_bounds__(256)
void x_convert_kernel(const float* __restrict__ x) {
    __shared__ float tile[128][68];
    const int y  = blockIdx.x;
    const int n  = blockIdx.y;
    const int cg = blockIdx.z;
    const int t  = threadIdx.x;

    {
        const int c_local = t >> 1;
        const int xh = (t & 1) * 32;
        const float4* src = (const float4*)(x +
            (((size_t)(n * CC + cg * 128 + c_local) * HH + y) * WW) + xh);
        #pragma unroll
        for (int k = 0; k < 8; ++k) {
            float4 v = src[k];
            tile[c_local][xh + k * 4 + 0] = v.x;
            tile[c_local][xh + k * 4 + 1] = v.y;
            tile[c_local][xh + k * 4 + 2] = v.z;
            tile[c_local][xh + k * 4 + 3] = v.w;
        }
    }
    __syncthreads();

    #pragma unroll
    for (int k = 0; k < 4; ++k) {
        const int q = t + 256 * k;
        const int xcol = q >> 4;
        const int cc = (q & 15) * 8;
        __align__(16) __nv_bfloat16 hv[8];
        __align__(16) __nv_bfloat16 lv[8];
        #pragma unroll
        for (int i = 0; i < 8; ++i) {
            float v = tile[cc + i][xcol];
            hv[i] = __float2bfloat16(v);
            lv[i] = __float2bfloat16(v - __bfloat162float(hv[i]));
        }
        const size_t dst = ((size_t)(n * HH + y) * WW + xcol) * 256 + cg * 128 + cc;
        *(uint4*)(g_xhi + dst) = *(const uint4*)hv;
        *(uint4*)(g_xlo + dst) = *(const uint4*)lv;
    }
}

// ---------------------------------------------------------------------------
// Kernel 3: implicit-GEMM conv with mma.sync.
// CTA: 128 px (2 rows x 64 cols) x 128 oc. 8 warps, warp tile 32x64.
// 36 stages = 9 taps x 4 chunks of 64 ch. bf16x3: hi*hi + hi*lo + lo*hi.
// SMEM: A[2 buf][2 prec][128][64] + B[2][2][128][64] bf16 = 128KB, cp.async
// double-buffered. Epilogue: smem transpose -> float4 NCHW stores.
// ---------------------------------------------------------------------------
#define PTILE 16384                     // one [128][64] bf16 tile
#define B_OFF (4 * PTILE)               // 65536
#define SMEM_DYN (8 * PTILE)            // 131072

struct StageCtx {
    const __nv_bfloat16* xsrc;          // prec-selected base
    const __nv_bfloat16* wsrc;
    uint32_t sbase;
    int n, y0, oc0, p, r, rl, xc;
};

__device__ __forceinline__ void issue_stage(const StageCtx& c, int s, int buf) {
    const int chunk = s / 9;
    const int tap = s - chunk * 9;
    const int dy = tap / 3 - 1;
    const int dx = tap % 3 - 1;
    const int c0 = chunk * 64;

    const int gy = c.y0 + c.rl + dy;
    const int gx = c.xc + dx;
    const bool valid = ((unsigned)gy < 64u) && ((unsigned)gx < 64u);
    const __nv_bfloat16* asrc = valid
        ? c.xsrc + (((size_t)(c.n * HH + gy) * WW + gx) * 256 + c0)
        : c.xsrc;
    const uint32_t nb = valid ? 16u : 0u;
    const uint32_t rowoff = (uint32_t)c.r * 128;
    const uint32_t rx = (uint32_t)(c.r & 7);

    uint32_t adst = c.sbase + (uint32_t)(buf * 2 + c.p) * PTILE + rowoff;
    #pragma unroll
    for (int i = 0; i < 8; ++i)
        cp_async16(adst + (((uint32_t)i ^ rx) << 4), asrc + i * 8, nb);

    const __nv_bfloat16* bsrc =
        c.wsrc + ((size_t)(tap * 256 + c.oc0 + c.r) * 256 + c0);
    uint32_t bdst = c.sbase + B_OFF + (uint32_t)(buf * 2 + c.p) * PTILE + rowoff;
    #pragma unroll
    for (int i = 0; i < 8; ++i)
        cp_async16(bdst + (((uint32_t)i ^ rx) << 4), bsrc + i * 8, 16u);
}

__global__ __launch_bounds__(256, 1)
void conv_mma_kernel(float* __restrict__ out) {
    extern __shared__ char dsm[];
    const uint32_t sbase = smem_u32(dsm);

    const int t = threadIdx.x;
    const int lane = t & 31;
    const int wid = t >> 5;
    const int warp_m = wid & 3;
    const int warp_n = wid >> 2;
    const int y0 = blockIdx.x * 2;
    const int n = blockIdx.y;
    const int oc0 = blockIdx.z * 128;

    float acc[2][8][4];
    #pragma unroll
    for (int mi = 0; mi < 2; ++mi)
        #pragma unroll
        for (int ni = 0; ni < 8; ++ni)
            #pragma unroll
            for (int k = 0; k < 4; ++k) acc[mi][ni][k] = 0.f;

    StageCtx ctx;
    ctx.p = t >> 7;
    ctx.r = t & 127;
    ctx.rl = ctx.r >> 6;
    ctx.xc = ctx.r & 63;
    ctx.xsrc = ctx.p ? g_xlo : g_xhi;
    ctx.wsrc = ctx.p ? g_wlo : g_whi;
    ctx.sbase = sbase;
    ctx.n = n; ctx.y0 = y0; ctx.oc0 = oc0;

    // ldmatrix per-thread row components
    const int la = lane & 15;                       // A row within 16
    const int ca = lane >> 4;                       // A k-chunk select
    const int lb = (lane & 7) + ((lane >> 4) << 3); // B row within 16
    const int cb = (lane >> 3) & 1;                 // B k-chunk select

    issue_stage(ctx, 0, 0);
    cp_commit();

    for (int s = 0; s < 36; ++s) {
        if (s + 1 < 36) {
            issue_stage(ctx, s + 1, (s + 1) & 1);
            cp_commit();
            cp_wait<1>();
        } else {
            cp_wait<0>();
        }
        __syncthreads();

        const int buf = s & 1;
        const uint32_t abase = sbase + (uint32_t)(buf * 2) * PTILE;
        const uint32_t bbase = sbase + B_OFF + (uint32_t)(buf * 2) * PTILE;

        #pragma unroll
        for (int ks = 0; ks < 4; ++ks) {
            uint32_t ah[2][4], al[2][4], bh[4][4], bl[4][4];
            #pragma unroll
            for (int mi = 0; mi < 2; ++mi) {
                const int row = warp_m * 32 + mi * 16 + la;
                const uint32_t off = (uint32_t)row * 128 +
                    ((uint32_t)((ks * 2 + ca) ^ (row & 7)) << 4);
                ldmx4(ah[mi], abase + off);
                ldmx4(al[mi], abase + PTILE + off);
            }
            #pragma unroll
            for (int nj = 0; nj < 4; ++nj) {
                const int row = warp_n * 64 + nj * 16 + lb;
                const uint32_t off = (uint32_t)row * 128 +
                    ((uint32_t)((ks * 2 + cb) ^ (row & 7)) << 4);
                ldmx4(bh[nj], bbase + off);
                ldmx4(bl[nj], bbase + PTILE + off);
            }
            #pragma unroll
            for (int mi = 0; mi < 2; ++mi) {
                #pragma unroll
                for (int ni = 0; ni < 8; ++ni) {
                    const uint32_t* ph = &bh[ni >> 1][(ni & 1) * 2];
                    const uint32_t* pl = &bl[ni >> 1][(ni & 1) * 2];
                    mma16816(acc[mi][ni], ah[mi], ph);   // hi*hi
                    mma16816(acc[mi][ni], ah[mi], pl);   // hi*lo
                    mma16816(acc[mi][ni], al[mi], ph);   // lo*hi
                }
            }
        }
        __syncthreads();
    }

    // ---- epilogue: transpose through smem, coalesced float4 stores ----
    float* sC = (float*)dsm;                 // [128 oc][132 px-padded]
    const int r0 = lane >> 2;
    const int col0 = (lane & 3) * 2;
    #pragma unroll
    for (int mi = 0; mi < 2; ++mi) {
        #pragma unroll
        for (int ni = 0; ni < 8; ++ni) {
            const int px = warp_m * 32 + mi * 16 + r0;
            const int oc = warp_n * 64 + ni * 8 + col0;
            sC[oc * 132 + px]           = acc[mi][ni][0];
            sC[(oc + 1) * 132 + px]     = acc[mi][ni][1];
            sC[oc * 132 + px + 8]       = acc[mi][ni][2];
            sC[(oc + 1) * 132 + px + 8] = acc[mi][ni][3];
        }
    }
    __syncthreads();

    #pragma unroll
    for (int it = 0; it < 16; ++it) {
        const int linear = t + it * 256;
        const int oc = linear >> 5;
        const int pg = linear & 31;
        float4 v = *(const float4*)&sC[oc * 132 + pg * 4];
        const int yy = y0 + (pg >> 4);
        const int xx = (pg & 15) * 4;
        *(float4*)&out[((size_t)(n * OCC + oc0 + oc) * HH + yy) * WW + xx] = v;
    }
}

// ---------------------------------------------------------------------------
extern "C" void kernel_launch(void* const* d_in, const int* in_sizes, int n_in,
                              void* d_out, int out_size) {
    const float* x  = (const float*)d_in[0];
    const float* z  = (const float*)d_in[1];
    const float* W1 = (const float*)d_in[2];
    const float* B1 = (const float*)d_in[3];
    const float* W2 = (const float*)d_in[4];
    const float* B2 = (const float*)d_in[5];
    float* out = (float*)d_out;

    weight_gen_kernel<<<256, 256>>>(z, W1, B1, W2, B2);

    dim3 tg(64, 32, 2);
    x_convert_kernel<<<tg, 256>>>(x);

    cudaFuncSetAttribute(conv_mma_kernel,
                         cudaFuncAttributeMaxDynamicSharedMemorySize, SMEM_DYN);
    conv_mma_kernel<<<dim3(32, 32, 2), 256, SMEM_DYN>>>(out);
}

// round 4
// speedup vs baseline: 2.1608x; 1.3506x over previous
#include <cuda_runtime.h>
#include <cuda_bf16.h>
#include <cstdint>

// ===========================================================================
// HyperConvS: weight-gen -> NHWC bf16 hi/lo convert -> implicit GEMM conv
// (mma.sync bf16x3, fp32 accum). Conv reuses one halo A-tile across all 9
// taps via ldmatrix per-lane row gather.
// ===========================================================================

#define HH 64
#define WW 64
#define CC 256
#define OCC 256

__device__ __nv_bfloat16 g_xhi[32 * 64 * 64 * 256];   // NHWC
__device__ __nv_bfloat16 g_xlo[32 * 64 * 64 * 256];
__device__ __nv_bfloat16 g_whi[9 * 256 * 256];        // [tap][oc][ic]
__device__ __nv_bfloat16 g_wlo[9 * 256 * 256];

// ---- helpers ----
__device__ __forceinline__ uint32_t smem_u32(const void* p) {
    uint32_t a;
    asm("{ .reg .u64 t; cvta.to.shared.u64 t, %1; cvt.u32.u64 %0, t; }"
        : "=r"(a) : "l"(p));
    return a;
}
__device__ __forceinline__ void cp_async16(uint32_t dst, const void* src, uint32_t nbytes) {
    asm volatile("cp.async.cg.shared.global [%0], [%1], 16, %2;"
                 :: "r"(dst), "l"(src), "r"(nbytes) : "memory");
}
__device__ __forceinline__ void cp_commit() {
    asm volatile("cp.async.commit_group;" ::: "memory");
}
template <int N>
__device__ __forceinline__ void cp_wait() {
    asm volatile("cp.async.wait_group %0;" :: "n"(N) : "memory");
}
__device__ __forceinline__ void ldmx4(uint32_t* r, uint32_t addr) {
    asm volatile("ldmatrix.sync.aligned.m8n8.x4.shared.b16 {%0,%1,%2,%3}, [%4];"
                 : "=r"(r[0]), "=r"(r[1]), "=r"(r[2]), "=r"(r[3]) : "r"(addr));
}
__device__ __forceinline__ void mma16816(float* c, const uint32_t* a, const uint32_t* b) {
    asm volatile(
        "mma.sync.aligned.m16n8k16.row.col.f32.bf16.bf16.f32 "
        "{%0,%1,%2,%3}, {%4,%5,%6,%7}, {%8,%9}, {%0,%1,%2,%3};"
        : "+f"(c[0]), "+f"(c[1]), "+f"(c[2]), "+f"(c[3])
        : "r"(a[0]), "r"(a[1]), "r"(a[2]), "r"(a[3]), "r"(b[0]), "r"(b[1]));
}

// ---------------------------------------------------------------------------
// Kernel 1: weight generation. Block = (b, l-group of 16). Smem-transposed
// W1 [n][d] (pad 65) and W2 [d][k] (pad 149): all inner-loop shared loads
// are lane-consecutive (conflict-free) with broadcast second operand.
// ---------------------------------------------------------------------------
__global__ __launch_bounds__(256)
void weight_gen_kernel(const float* __restrict__ z,
                       const float* __restrict__ W1,
                       const float* __restrict__ B1,
                       const float* __restrict__ W2,
                       const float* __restrict__ B2) {
    __shared__ float w1t[64 * 65];     // [n][d]
    __shared__ float w2t[64 * 149];    // [d][k]
    __shared__ float z_s[16 * 64];
    __shared__ float a_s[16 * 64];
    const int b  = blockIdx.x;         // 0..15  (block row of MLP)
    const int lg = blockIdx.y;         // 0..15  (latent group = o_blk)
    const int t  = threadIdx.x;

    for (int i = t; i < 64 * 64; i += 256) {
        const int d = i >> 6, n = i & 63;
        w1t[n * 65 + d] = W1[(b * 64 + d) * 64 + n];
    }
    for (int i = t; i < 144 * 64; i += 256) {
        const int k = i >> 6, d = i & 63;
        w2t[d * 149 + k] = W2[(b * 144 + k) * 64 + d];
    }
    for (int i = t; i < 1024; i += 256) z_s[i] = z[lg * 16 * 64 + i];
    __syncthreads();

    // layer 1: 1024 outputs (16 l x 64 d)
    for (int i = t; i < 1024; i += 256) {
        const int il = i >> 6, d = i & 63;
        float s = B1[b * 64 + d];
        #pragma unroll 16
        for (int n = 0; n < 64; ++n) s += w1t[n * 65 + d] * z_s[il * 64 + n];
        a_s[i] = s;
    }
    __syncthreads();

    // layer 2 + scatter: 2304 outputs (16 l x 144 k)
    for (int i = t; i < 2304; i += 256) {
        const int il = i / 144, k = i - il * 144;
        float s = B2[b * 144 + k];
        #pragma unroll 16
        for (int d = 0; d < 64; ++d) s += w2t[d * 149 + k] * a_s[il * 64 + d];
        const int b2 = k / 9;
        const int tap = k - b2 * 9;
        const int o = lg * 16 + b2;
        const int ic = il * 16 + b;
        __nv_bfloat16 hi = __float2bfloat16(s);
        __nv_bfloat16 lo = __float2bfloat16(s - __bfloat162float(hi));
        g_whi[(tap * 256 + o) * 256 + ic] = hi;
        g_wlo[(tap * 256 + o) * 256 + ic] = lo;
    }
}

// ---------------------------------------------------------------------------
// Kernel 2: NCHW fp32 -> NHWC bf16 hi/lo transpose.
// ---------------------------------------------------------------------------
__global__ __launch_bounds__(256)
void x_convert_kernel(const float* __restrict__ x) {
    __shared__ float tile[128][68];
    const int y  = blockIdx.x;
    const int n  = blockIdx.y;
    const int cg = blockIdx.z;
    const int t  = threadIdx.x;

    {
        const int c_local = t >> 1;
        const int xh = (t & 1) * 32;
        const float4* src = (const float4*)(x +
            (((size_t)(n * CC + cg * 128 + c_local) * HH + y) * WW) + xh);
        #pragma unroll
        for (int k = 0; k < 8; ++k) {
            float4 v = src[k];
            tile[c_local][xh + k * 4 + 0] = v.x;
            tile[c_local][xh + k * 4 + 1] = v.y;
            tile[c_local][xh + k * 4 + 2] = v.z;
            tile[c_local][xh + k * 4 + 3] = v.w;
        }
    }
    __syncthreads();

    #pragma unroll
    for (int k = 0; k < 4; ++k) {
        const int q = t + 256 * k;
        const int xcol = q >> 4;
        const int cc = (q & 15) * 8;
        __align__(16) __nv_bfloat16 hv[8];
        __align__(16) __nv_bfloat16 lv[8];
        #pragma unroll
        for (int i = 0; i < 8; ++i) {
            float v = tile[cc + i][xcol];
            hv[i] = __float2bfloat16(v);
            lv[i] = __float2bfloat16(v - __bfloat162float(hv[i]));
        }
        const size_t dst = ((size_t)(n * HH + y) * WW + xcol) * 256 + cg * 128 + cc;
        *(uint4*)(g_xhi + dst) = *(const uint4*)hv;
        *(uint4*)(g_xlo + dst) = *(const uint4*)lv;
    }
}

// ---------------------------------------------------------------------------
// Kernel 3: implicit-GEMM conv.
// CTA: 128 px (2 rows x 64 cols) x 128 oc, 8 warps (warp 32x64).
// A: halo tile [2 prec][264 rows = 4x66][64 ch] loaded ONCE per 64-ch chunk
//    (borders zero-filled by cp.async src-size 0); all 9 taps read it via
//    ldmatrix per-lane row gather.
// B: [2 buf][2 prec][128 oc][64 ch], double-buffered per (tap,chunk) stage.
// ---------------------------------------------------------------------------
#define A_PTILE 33792u                 // 264 rows * 128 B
#define A_REGION (2 * A_PTILE)         // 67584
#define B_PTILE 16384u
#define B_OFF A_REGION
#define SMEM_DYN (A_REGION + 4 * B_PTILE)   // 133120

struct Ctx {
    uint32_t sbase;
    int n, y0, oc0;
};

__device__ __forceinline__ void issue_A(const Ctx& c, int chunk, int t) {
    const int c0 = chunk * 64;
    #pragma unroll
    for (int it = 0; it < 3; ++it) {
        const int idx = t + it * 256;
        if (idx >= 528) break;
        const int pr = idx & 1;
        const int r = idx >> 1;                   // 0..263 halo row
        const int hrow = r / 66;
        const int hcol = r - hrow * 66;
        const int gy = c.y0 - 1 + hrow;
        const int gx = hcol - 1;
        const bool valid = ((unsigned)gy < 64u) && ((unsigned)gx < 64u);
        const __nv_bfloat16* xp = pr ? g_xlo : g_xhi;
        const __nv_bfloat16* src = valid
            ? xp + (((size_t)(c.n * HH + gy) * WW + gx) * 256 + c0)
            : xp;
        const uint32_t nb = valid ? 16u : 0u;
        const uint32_t dst = c.sbase + pr * A_PTILE + (uint32_t)r * 128;
        const uint32_t rx = (uint32_t)(r & 7);
        #pragma unroll
        for (int i = 0; i < 8; ++i)
            cp_async16(dst + (((uint32_t)i ^ rx) << 4), src + i * 8, nb);
    }
}

__device__ __forceinline__ void issue_B(const Ctx& c, int s, int t) {
    const int chunk = s / 9;
    const int tap = s - chunk * 9;
    const int buf = s & 1;
    const int pr = t >> 7;
    const int r = t & 127;
    const __nv_bfloat16* wp = pr ? g_wlo : g_whi;
    const __nv_bfloat16* src =
        wp + ((size_t)(tap * 256 + c.oc0 + r) * 256 + chunk * 64);
    const uint32_t dst = c.sbase + B_OFF + (uint32_t)(buf * 2 + pr) * B_PTILE
                       + (uint32_t)r * 128;
    const uint32_t rx = (uint32_t)(r & 7);
    #pragma unroll
    for (int i = 0; i < 8; ++i)
        cp_async16(dst + (((uint32_t)i ^ rx) << 4), src + i * 8, 16u);
}

__global__ __launch_bounds__(256, 1)
void conv_mma_kernel(float* __restrict__ out) {
    extern __shared__ char dsm[];
    const uint32_t sbase = smem_u32(dsm);

    const int t = threadIdx.x;
    const int lane = t & 31;
    const int wid = t >> 5;
    const int warp_m = wid & 3;
    const int warp_n = wid >> 2;
    const int y0 = blockIdx.x * 2;
    const int n = blockIdx.y;
    const int oc0 = blockIdx.z * 128;

    Ctx ctx; ctx.sbase = sbase; ctx.n = n; ctx.y0 = y0; ctx.oc0 = oc0;

    float acc[2][8][4];
    #pragma unroll
    for (int mi = 0; mi < 2; ++mi)
        #pragma unroll
        for (int ni = 0; ni < 8; ++ni)
            #pragma unroll
            for (int k = 0; k < 4; ++k) acc[mi][ni][k] = 0.f;

    const int la = lane & 15;
    const int ca = lane >> 4;
    const int lb = (lane & 7) + ((lane >> 4) << 3);
    const int cb = (lane >> 3) & 1;

    // base pixel coords for the two A fragments (before tap shift)
    int arl[2], axc[2];
    #pragma unroll
    for (int mi = 0; mi < 2; ++mi) {
        const int m = warp_m * 32 + mi * 16 + la;
        arl[mi] = m >> 6;
        axc[mi] = m & 63;
    }

    issue_A(ctx, 0, t);
    issue_B(ctx, 0, t);
    cp_commit();

    for (int s = 0; s < 36; ++s) {
        if (s < 35) {
            issue_B(ctx, s + 1, t);
            cp_commit();
            cp_wait<1>();
        } else {
            cp_wait<0>();
        }
        __syncthreads();

        const int chunkS = s / 9;
        const int tap = s - chunkS * 9;
        const int dy = tap / 3 - 1;
        const int dx = tap % 3 - 1;
        const int buf = s & 1;
        const uint32_t bbase = sbase + B_OFF + (uint32_t)(buf * 2) * B_PTILE;

        // per-lane gathered A rows for this tap
        uint32_t aoff[2], axr[2];
        #pragma unroll
        for (int mi = 0; mi < 2; ++mi) {
            const int r = (arl[mi] + 1 + dy) * 66 + (axc[mi] + 1 + dx);
            aoff[mi] = (uint32_t)r * 128;
            axr[mi] = (uint32_t)(r & 7);
        }

        #pragma unroll
        for (int ks = 0; ks < 4; ++ks) {
            uint32_t ah[2][4], al[2][4], bh[4][4], bl[4][4];
            #pragma unroll
            for (int mi = 0; mi < 2; ++mi) {
                const uint32_t off = aoff[mi] +
                    (((uint32_t)(ks * 2 + ca) ^ axr[mi]) << 4);
                ldmx4(ah[mi], sbase + off);
                ldmx4(al[mi], sbase + A_PTILE + off);
            }
            #pragma unroll
            for (int nj = 0; nj < 4; ++nj) {
                const int row = warp_n * 64 + nj * 16 + lb;
                const uint32_t off = (uint32_t)row * 128 +
                    ((uint32_t)((ks * 2 + cb) ^ (row & 7)) << 4);
                ldmx4(bh[nj], bbase + off);
                ldmx4(bl[nj], bbase + B_PTILE + off);
            }
            #pragma unroll
            for (int mi = 0; mi < 2; ++mi) {
                #pragma unroll
                for (int ni = 0; ni < 8; ++ni) {
                    const uint32_t* ph = &bh[ni >> 1][(ni & 1) * 2];
                    const uint32_t* pl = &bl[ni >> 1][(ni & 1) * 2];
                    mma16816(acc[mi][ni], ah[mi], ph);   // hi*hi
                    mma16816(acc[mi][ni], ah[mi], pl);   // hi*lo
                    mma16816(acc[mi][ni], al[mi], ph);   // lo*hi
                }
            }
        }
        __syncthreads();

        if ((s == 8 || s == 17 || s == 26)) {
            issue_A(ctx, (s + 1) / 9, t);
            cp_commit();
        }
    }

    // ---- epilogue: transpose through smem (reuses A region), float4 stores
    float* sC = (float*)dsm;                 // [128 oc][132 px]
    const int r0 = lane >> 2;
    const int col0 = (lane & 3) * 2;
    #pragma unroll
    for (int mi = 0; mi < 2; ++mi) {
        #pragma unroll
        for (int ni = 0; ni < 8; ++ni) {
            const int px = warp_m * 32 + mi * 16 + r0;
            const int oc = warp_n * 64 + ni * 8 + col0;
            sC[oc * 132 + px]           = acc[mi][ni][0];
            sC[(oc + 1) * 132 + px]     = acc[mi][ni][1];
            sC[oc * 132 + px + 8]       = acc[mi][ni][2];
            sC[(oc + 1) * 132 + px + 8] = acc[mi][ni][3];
        }
    }
    __syncthreads();

    #pragma unroll
    for (int it = 0; it < 16; ++it) {
        const int linear = t + it * 256;
        const int oc = linear >> 5;
        const int pg = linear & 31;
        float4 v = *(const float4*)&sC[oc * 132 + pg * 4];
        const int yy = y0 + (pg >> 4);
        const int xx = (pg & 15) * 4;
        *(float4*)&out[((size_t)(n * OCC + oc0 + oc) * HH + yy) * WW + xx] = v;
    }
}

// ---------------------------------------------------------------------------
extern "C" void kernel_launch(void* const* d_in, const int* in_sizes, int n_in,
                              void* d_out, int out_size) {
    const float* x  = (const float*)d_in[0];
    const float* z  = (const float*)d_in[1];
    const float* W1 = (const float*)d_in[2];
    const float* B1 = (const float*)d_in[3];
    const float* W2 = (const float*)d_in[4];
    const float* B2 = (const float*)d_in[5];
    float* out = (float*)d_out;

    weight_gen_kernel<<<dim3(16, 16), 256>>>(z, W1, B1, W2, B2);

    dim3 tg(64, 32, 2);
    x_convert_kernel<<<tg, 256>>>(x);

    cudaFuncSetAttribute(conv_mma_kernel,
                         cudaFuncAttributeMaxDynamicSharedMemorySize, SMEM_DYN);
    conv_mma_kernel<<<dim3(32, 32, 2), 256, SMEM_DYN>>>(out);
}

// round 5
// speedup vs baseline: 2.9661x; 1.3727x over previous
#include <cuda_runtime.h>
#include <cuda_bf16.h>
#include <cstdint>

// ===========================================================================
// HyperConvS: weight-gen -> NHWC bf16 hi/lo convert -> implicit GEMM conv
// (mma.sync bf16x3, fp32 accum). M=256 x N=128 CTA, 512 threads (4 warps/
// SMSP), halo A-tile reused across 9 taps, triple-buffered B, 1 barrier/stage.
// ===========================================================================

#define HH 64
#define WW 64
#define CC 256
#define OCC 256

__device__ __nv_bfloat16 g_xhi[32 * 64 * 64 * 256];   // NHWC
__device__ __nv_bfloat16 g_xlo[32 * 64 * 64 * 256];
__device__ __nv_bfloat16 g_whi[9 * 256 * 256];        // [tap][oc][ic]
__device__ __nv_bfloat16 g_wlo[9 * 256 * 256];

// ---- helpers ----
__device__ __forceinline__ uint32_t smem_u32(const void* p) {
    uint32_t a;
    asm("{ .reg .u64 t; cvta.to.shared.u64 t, %1; cvt.u32.u64 %0, t; }"
        : "=r"(a) : "l"(p));
    return a;
}
__device__ __forceinline__ void cp_async16(uint32_t dst, const void* src, uint32_t nbytes) {
    asm volatile("cp.async.cg.shared.global [%0], [%1], 16, %2;"
                 :: "r"(dst), "l"(src), "r"(nbytes) : "memory");
}
__device__ __forceinline__ void cp_commit() {
    asm volatile("cp.async.commit_group;" ::: "memory");
}
template <int N>
__device__ __forceinline__ void cp_wait() {
    asm volatile("cp.async.wait_group %0;" :: "n"(N) : "memory");
}
__device__ __forceinline__ void ldmx4(uint32_t* r, uint32_t addr) {
    asm volatile("ldmatrix.sync.aligned.m8n8.x4.shared.b16 {%0,%1,%2,%3}, [%4];"
                 : "=r"(r[0]), "=r"(r[1]), "=r"(r[2]), "=r"(r[3]) : "r"(addr));
}
__device__ __forceinline__ void mma16816(float* c, const uint32_t* a, const uint32_t* b) {
    asm volatile(
        "mma.sync.aligned.m16n8k16.row.col.f32.bf16.bf16.f32 "
        "{%0,%1,%2,%3}, {%4,%5,%6,%7}, {%8,%9}, {%0,%1,%2,%3};"
        : "+f"(c[0]), "+f"(c[1]), "+f"(c[2]), "+f"(c[3])
        : "r"(a[0]), "r"(a[1]), "r"(a[2]), "r"(a[3]), "r"(b[0]), "r"(b[1]));
}

// ---------------------------------------------------------------------------
// Kernel 1: weight generation (smem-transposed MLP weights).
// ---------------------------------------------------------------------------
__global__ __launch_bounds__(256)
void weight_gen_kernel(const float* __restrict__ z,
                       const float* __restrict__ W1,
                       const float* __restrict__ B1,
                       const float* __restrict__ W2,
                       const float* __restrict__ B2) {
    __shared__ float w1t[64 * 65];     // [n][d]
    __shared__ float w2t[64 * 149];    // [d][k]
    __shared__ float z_s[16 * 64];
    __shared__ float a_s[16 * 64];
    const int b  = blockIdx.x;
    const int lg = blockIdx.y;
    const int t  = threadIdx.x;

    for (int i = t; i < 64 * 64; i += 256) {
        const int d = i >> 6, n = i & 63;
        w1t[n * 65 + d] = W1[(b * 64 + d) * 64 + n];
    }
    for (int i = t; i < 144 * 64; i += 256) {
        const int k = i >> 6, d = i & 63;
        w2t[d * 149 + k] = W2[(b * 144 + k) * 64 + d];
    }
    for (int i = t; i < 1024; i += 256) z_s[i] = z[lg * 16 * 64 + i];
    __syncthreads();

    for (int i = t; i < 1024; i += 256) {
        const int il = i >> 6, d = i & 63;
        float s = B1[b * 64 + d];
        #pragma unroll 16
        for (int n = 0; n < 64; ++n) s += w1t[n * 65 + d] * z_s[il * 64 + n];
        a_s[i] = s;
    }
    __syncthreads();

    for (int i = t; i < 2304; i += 256) {
        const int il = i / 144, k = i - il * 144;
        float s = B2[b * 144 + k];
        #pragma unroll 16
        for (int d = 0; d < 64; ++d) s += w2t[d * 149 + k] * a_s[il * 64 + d];
        const int b2 = k / 9;
        const int tap = k - b2 * 9;
        const int o = lg * 16 + b2;
        const int ic = il * 16 + b;
        __nv_bfloat16 hi = __float2bfloat16(s);
        __nv_bfloat16 lo = __float2bfloat16(s - __bfloat162float(hi));
        g_whi[(tap * 256 + o) * 256 + ic] = hi;
        g_wlo[(tap * 256 + o) * 256 + ic] = lo;
    }
}

// ---------------------------------------------------------------------------
// Kernel 2: NCHW fp32 -> NHWC bf16 hi/lo transpose.
// ---------------------------------------------------------------------------
__global__ __launch_bounds__(256)
void x_convert_kernel(const float* __restrict__ x) {
    __shared__ float tile[128][68];
    const int y  = blockIdx.x;
    const int n  = blockIdx.y;
    const int cg = blockIdx.z;
    const int t  = threadIdx.x;

    {
        const int c_local = t >> 1;
        const int xh = (t & 1) * 32;
        const float4* src = (const float4*)(x +
            (((size_t)(n * CC + cg * 128 + c_local) * HH + y) * WW) + xh);
        #pragma unroll
        for (int k = 0; k < 8; ++k) {
            float4 v = src[k];
            tile[c_local][xh + k * 4 + 0] = v.x;
            tile[c_local][xh + k * 4 + 1] = v.y;
            tile[c_local][xh + k * 4 + 2] = v.z;
            tile[c_local][xh + k * 4 + 3] = v.w;
        }
    }
    __syncthreads();

    #pragma unroll
    for (int k = 0; k < 4; ++k) {
        const int q = t + 256 * k;
        const int xcol = q >> 4;
        const int cc = (q & 15) * 8;
        __align__(16) __nv_bfloat16 hv[8];
        __align__(16) __nv_bfloat16 lv[8];
        #pragma unroll
        for (int i = 0; i < 8; ++i) {
            float v = tile[cc + i][xcol];
            hv[i] = __float2bfloat16(v);
            lv[i] = __float2bfloat16(v - __bfloat162float(hv[i]));
        }
        const size_t dst = ((size_t)(n * HH + y) * WW + xcol) * 256 + cg * 128 + cc;
        *(uint4*)(g_xhi + dst) = *(const uint4*)hv;
        *(uint4*)(g_xlo + dst) = *(const uint4*)lv;
    }
}

// ---------------------------------------------------------------------------
// Kernel 3: implicit-GEMM conv.
// CTA: 256 px (4 rows x 64 cols) x 128 oc, 512 threads / 16 warps
// (warp tile 32x64, warp_m = wid&7, warp_n = wid>>3).
// A: halo [2 prec][396 = 6x66 rows][64 ch], loaded once per chunk.
// B: [3 buf][2 prec][128 oc][64 ch], triple-buffered, depth-2 prefetch.
// ---------------------------------------------------------------------------
#define A_PTILE 50688u                 // 396 rows * 128 B
#define A_REGION (2 * A_PTILE)         // 101376
#define B_PTILE 16384u
#define B_OFF A_REGION
#define SMEM_DYN (A_REGION + 6 * B_PTILE)   // 199680

struct Ctx {
    uint32_t sbase;
    int n, y0, oc0;
};

__device__ __forceinline__ void issue_A(const Ctx& c, int chunk, int t) {
    const int c0 = chunk * 64;
    #pragma unroll
    for (int it = 0; it < 2; ++it) {
        const int idx = t + it * 512;
        if (idx >= 792) break;
        const int pr = idx & 1;
        const int r = idx >> 1;                   // 0..395 halo row
        const int hrow = r / 66;
        const int hcol = r - hrow * 66;
        const int gy = c.y0 - 1 + hrow;
        const int gx = hcol - 1;
        const bool valid = ((unsigned)gy < 64u) && ((unsigned)gx < 64u);
        const __nv_bfloat16* xp = pr ? g_xlo : g_xhi;
        const __nv_bfloat16* src = valid
            ? xp + (((size_t)(c.n * HH + gy) * WW + gx) * 256 + c0)
            : xp;
        const uint32_t nb = valid ? 16u : 0u;
        const uint32_t dst = c.sbase + pr * A_PTILE + (uint32_t)r * 128;
        const uint32_t rx = (uint32_t)(r & 7);
        #pragma unroll
        for (int i = 0; i < 8; ++i)
            cp_async16(dst + (((uint32_t)i ^ rx) << 4), src + i * 8, nb);
    }
}

__device__ __forceinline__ void issue_B(const Ctx& c, int s, int t) {
    const int chunk = s / 9;
    const int tap = s - chunk * 9;
    const int buf = s % 3;
    const int pr = t >> 8;
    const int rem = t & 255;
    const int r = rem >> 1;
    const int half = rem & 1;
    const __nv_bfloat16* wp = pr ? g_wlo : g_whi;
    const __nv_bfloat16* src =
        wp + ((size_t)(tap * 256 + c.oc0 + r) * 256 + chunk * 64);
    const uint32_t dst = c.sbase + B_OFF + (uint32_t)(buf * 2 + pr) * B_PTILE
                       + (uint32_t)r * 128;
    const uint32_t rx = (uint32_t)(r & 7);
    #pragma unroll
    for (int i = 0; i < 4; ++i) {
        const uint32_t ch = (uint32_t)(half * 4 + i);
        cp_async16(dst + ((ch ^ rx) << 4), src + ch * 8, 16u);
    }
}

__global__ __launch_bounds__(512, 1)
void conv_mma_kernel(float* __restrict__ out) {
    extern __shared__ char dsm[];
    const uint32_t sbase = smem_u32(dsm);

    const int t = threadIdx.x;
    const int lane = t & 31;
    const int wid = t >> 5;
    const int warp_m = wid & 7;
    const int warp_n = wid >> 3;
    const int y0 = blockIdx.x * 4;
    const int n = blockIdx.y;
    const int oc0 = blockIdx.z * 128;

    Ctx ctx; ctx.sbase = sbase; ctx.n = n; ctx.y0 = y0; ctx.oc0 = oc0;

    float acc[2][8][4];
    #pragma unroll
    for (int mi = 0; mi < 2; ++mi)
        #pragma unroll
        for (int ni = 0; ni < 8; ++ni)
            #pragma unroll
            for (int k = 0; k < 4; ++k) acc[mi][ni][k] = 0.f;

    const int la = lane & 15;
    const int ca = lane >> 4;
    const int lb = (lane & 7) + ((lane >> 4) << 3);
    const int cb = (lane >> 3) & 1;

    int arl[2], axc[2];
    #pragma unroll
    for (int mi = 0; mi < 2; ++mi) {
        const int m = warp_m * 32 + mi * 16 + la;   // 0..255
        arl[mi] = m >> 6;
        axc[mi] = m & 63;
    }

    // prologue: A(0)+B(0) one group, B(1) second group
    issue_A(ctx, 0, t);
    issue_B(ctx, 0, t);
    cp_commit();
    issue_B(ctx, 1, t);
    cp_commit();

    for (int s = 0; s < 36; ++s) {
        if ((s > 0 && s % 9 == 0) || s == 35) cp_wait<0>();
        else cp_wait<1>();
        __syncthreads();

        if (s + 2 < 36) {
            issue_B(ctx, s + 2, t);
            cp_commit();
        }

        const int chunkS = s / 9;
        const int tap = s - chunkS * 9;
        const int dy = tap / 3 - 1;
        const int dx = tap % 3 - 1;
        const int buf = s % 3;
        const uint32_t bbase = sbase + B_OFF + (uint32_t)(buf * 2) * B_PTILE;

        uint32_t aoff[2], axr[2];
        #pragma unroll
        for (int mi = 0; mi < 2; ++mi) {
            const int r = (arl[mi] + 1 + dy) * 66 + (axc[mi] + 1 + dx);
            aoff[mi] = (uint32_t)r * 128;
            axr[mi] = (uint32_t)(r & 7);
        }

        #pragma unroll
        for (int ks = 0; ks < 4; ++ks) {
            uint32_t ah[2][4], al[2][4], bh[4][4], bl[4][4];
            #pragma unroll
            for (int mi = 0; mi < 2; ++mi) {
                const uint32_t off = aoff[mi] +
                    (((uint32_t)(ks * 2 + ca) ^ axr[mi]) << 4);
                ldmx4(ah[mi], sbase + off);
                ldmx4(al[mi], sbase + A_PTILE + off);
            }
            #pragma unroll
            for (int nj = 0; nj < 4; ++nj) {
                const int row = warp_n * 64 + nj * 16 + lb;
                const uint32_t off = (uint32_t)row * 128 +
                    ((uint32_t)((ks * 2 + cb) ^ (row & 7)) << 4);
                ldmx4(bh[nj], bbase + off);
                ldmx4(bl[nj], bbase + B_PTILE + off);
            }
            #pragma unroll
            for (int mi = 0; mi < 2; ++mi) {
                #pragma unroll
                for (int ni = 0; ni < 8; ++ni) {
                    const uint32_t* ph = &bh[ni >> 1][(ni & 1) * 2];
                    const uint32_t* pl = &bl[ni >> 1][(ni & 1) * 2];
                    mma16816(acc[mi][ni], ah[mi], ph);   // hi*hi
                    mma16816(acc[mi][ni], ah[mi], pl);   // hi*lo
                    mma16816(acc[mi][ni], al[mi], ph);   // lo*hi
                }
            }
        }

        if (s % 9 == 8 && s < 35) {
            __syncthreads();
            issue_A(ctx, s / 9 + 1, t);
            cp_commit();
        }
    }

    __syncthreads();

    // ---- epilogue: transpose through smem, coalesced float4 stores ----
    float* sC = (float*)dsm;                 // [128 oc][264 px-padded]
    const int r0 = lane >> 2;
    const int col0 = (lane & 3) * 2;
    #pragma unroll
    for (int mi = 0; mi < 2; ++mi) {
        #pragma unroll
        for (int ni = 0; ni < 8; ++ni) {
            const int px = warp_m * 32 + mi * 16 + r0;
            const int oc = warp_n * 64 + ni * 8 + col0;
            sC[oc * 264 + px]           = acc[mi][ni][0];
            sC[(oc + 1) * 264 + px]     = acc[mi][ni][1];
            sC[oc * 264 + px + 8]       = acc[mi][ni][2];
            sC[(oc + 1) * 264 + px + 8] = acc[mi][ni][3];
        }
    }
    __syncthreads();

    #pragma unroll
    for (int it = 0; it < 16; ++it) {
        const int linear = t + it * 512;
        const int oc = linear >> 6;          // 64 float4 per oc
        const int q = linear & 63;
        float4 v = *(const float4*)&sC[oc * 264 + q * 4];
        const int yy = y0 + (q >> 4);
        const int xx = (q & 15) * 4;
        *(float4*)&out[((size_t)(n * OCC + oc0 + oc) * HH + yy) * WW + xx] = v;
    }
}

// ---------------------------------------------------------------------------
extern "C" void kernel_launch(void* const* d_in, const int* in_sizes, int n_in,
                              void* d_out, int out_size) {
    const float* x  = (const float*)d_in[0];
    const float* z  = (const float*)d_in[1];
    const float* W1 = (const float*)d_in[2];
    const float* B1 = (const float*)d_in[3];
    const float* W2 = (const float*)d_in[4];
    const float* B2 = (const float*)d_in[5];
    float* out = (float*)d_out;

    weight_gen_kernel<<<dim3(16, 16), 256>>>(z, W1, B1, W2, B2);

    dim3 tg(64, 32, 2);
    x_convert_kernel<<<tg, 256>>>(x);

    cudaFuncSetAttribute(conv_mma_kernel,
                         cudaFuncAttributeMaxDynamicSharedMemorySize, SMEM_DYN);
    conv_mma_kernel<<<dim3(16, 32, 2), 512, SMEM_DYN>>>(out);
}